// round 14
// baseline (speedup 1.0000x reference)
#include <cuda_runtime.h>
#include <cuda_fp16.h>
#include <math.h>
#include <stdint.h>

#define SEQ 3072
#define HIDDEN 1280
#define NH 16
#define HD 80
#define RD 40
#define QKV_N (3 * HIDDEN)
#define KSPLIT 3

// Scratch (allocation-free rule: __device__ globals)
__device__ __half g_qkv16[SEQ * QKV_N];     // QKV GEMM output (fp16)
__device__ __half g_hs16[SEQ * HIDDEN];     // hidden_states fp16
__device__ __half g_qw16[HIDDEN * QKV_N];   // qkv_w fp16
__device__ __half g_ow16[HIDDEN * HIDDEN];  // o_w fp16
__device__ __half g_att16[SEQ * HIDDEN];    // attention output fp16
__device__ __half g_q16[NH * SEQ * HD];     // head-major, rope'd, pre-scaled (log2 dom)
__device__ __half g_k16[NH * SEQ * HD];     // head-major, rope'd
__device__ __half g_v16[NH * SEQ * HD];     // head-major
__device__ float  g_part[KSPLIT * NH * SEQ * HD];  // unnormalized partial O
__device__ float2 g_ml[KSPLIT * NH * SEQ];         // per-row (max(log2), sum)

// ---------------------------------------------------------------------------
// helpers
// ---------------------------------------------------------------------------
__device__ __forceinline__ uint32_t h2_as_u32(__half2 h) {
    union { __half2 h2; uint32_t u; } cvt;
    cvt.h2 = h;
    return cvt.u;
}

__device__ __forceinline__ void mma_f16(float* d, const uint32_t* a, const uint32_t* b) {
    asm volatile(
        "mma.sync.aligned.m16n8k16.row.col.f32.f16.f16.f32 "
        "{%0,%1,%2,%3},{%4,%5,%6,%7},{%8,%9},{%0,%1,%2,%3};"
        : "+f"(d[0]), "+f"(d[1]), "+f"(d[2]), "+f"(d[3])
        : "r"(a[0]), "r"(a[1]), "r"(a[2]), "r"(a[3]),
          "r"(b[0]), "r"(b[1]));
}

__device__ __forceinline__ void ldsm_x4(uint32_t* r, uint32_t addr) {
    asm volatile("ldmatrix.sync.aligned.m8n8.x4.shared.b16 {%0,%1,%2,%3},[%4];"
        : "=r"(r[0]), "=r"(r[1]), "=r"(r[2]), "=r"(r[3]) : "r"(addr));
}

__device__ __forceinline__ void ldsm_x4_t(uint32_t* r, uint32_t addr) {
    asm volatile("ldmatrix.sync.aligned.m8n8.x4.trans.shared.b16 {%0,%1,%2,%3},[%4];"
        : "=r"(r[0]), "=r"(r[1]), "=r"(r[2]), "=r"(r[3]) : "r"(addr));
}

__device__ __forceinline__ void cp16(uint32_t dst, const void* src) {
    asm volatile("cp.async.ca.shared.global [%0], [%1], 16;" :: "r"(dst), "l"(src));
}
__device__ __forceinline__ void cp_commit() { asm volatile("cp.async.commit_group;"); }
__device__ __forceinline__ void cp_wait0() { asm volatile("cp.async.wait_group 0;"); }
__device__ __forceinline__ void cp_wait1() { asm volatile("cp.async.wait_group 1;"); }

// ---------------------------------------------------------------------------
// Fused fp32 -> fp16 convert for hs, qkv_w, o_w (one launch).
// ---------------------------------------------------------------------------
#define N8_HS  (SEQ * HIDDEN / 8)          // 491520
#define N8_QW  (HIDDEN * QKV_N / 8)        // 614400
#define N8_OW  (HIDDEN * HIDDEN / 8)       // 204800
#define N8_ALL (N8_HS + N8_QW + N8_OW)

__global__ __launch_bounds__(256) void cvt_all(
    const float* __restrict__ hs, const float* __restrict__ qw,
    const float* __restrict__ ow)
{
    int idx = blockIdx.x * blockDim.x + threadIdx.x;
    if (idx >= N8_ALL) return;

    const float* src;
    __half* dst;
    int off;
    if (idx < N8_HS) {
        src = hs; dst = g_hs16; off = idx;
    } else if (idx < N8_HS + N8_QW) {
        src = qw; dst = g_qw16; off = idx - N8_HS;
    } else {
        src = ow; dst = g_ow16; off = idx - N8_HS - N8_QW;
    }

    float4 v0 = *reinterpret_cast<const float4*>(&src[off * 8]);
    float4 v1 = *reinterpret_cast<const float4*>(&src[off * 8 + 4]);
    __half2 h[4];
    h[0] = __floats2half2_rn(v0.x, v0.y);
    h[1] = __floats2half2_rn(v0.z, v0.w);
    h[2] = __floats2half2_rn(v1.x, v1.y);
    h[3] = __floats2half2_rn(v1.z, v1.w);
    *reinterpret_cast<uint4*>(&dst[off * 8]) = *reinterpret_cast<uint4*>(h);
}

// ---------------------------------------------------------------------------
// HGEMM: C[M,N] = A[M,K](fp16) @ B[K,N](fp16) + bias[N](fp32)
// BM=128 BN=128 BK=32, 128 threads = 4 warps (2m x 2n), warp tile m64 x n64.
// 3-stage cp.async ring, single barrier per iteration, 3 CTAs/SM.
// ---------------------------------------------------------------------------
#define GLDA 40
#define GLDB 136
#define A_STG (128 * GLDA)
#define B_STG (32 * GLDB)
#define NSTG 3
#define HG_SMEM ((NSTG * (A_STG + B_STG)) * 2)

__global__ __launch_bounds__(128, 3) void hgemm_bias(
    const __half* __restrict__ A, const __half* __restrict__ B,
    const float* __restrict__ bias, void* __restrict__ Cv,
    int M, int N, int K, int halfOut)
{
    extern __shared__ __half hsm[];
    __half* sA = hsm;
    __half* sB = hsm + NSTG * A_STG;

    const int tid  = threadIdx.x;
    const int wid  = tid >> 5;
    const int lane = tid & 31;
    const int wm   = wid >> 1;
    const int wn   = wid & 1;
    const int gid  = lane >> 2;
    const int tig  = lane & 3;
    const int j8   = lane & 7;
    const int grp  = lane >> 3;

    const int m0 = blockIdx.y * 128;
    const int n0 = blockIdx.x * 128;

    const uint32_t saBase = (uint32_t)__cvta_generic_to_shared(sA);
    const uint32_t sbBase = (uint32_t)__cvta_generic_to_shared(sB);

    const int aLane = ((grp & 1) * 8 + j8) * GLDA + (grp >> 1) * 8;
    const int bLane = ((grp & 1) * 8 + j8) * GLDB + (grp >> 1) * 8;

    float acc[4][8][4];
    #pragma unroll
    for (int i = 0; i < 4; i++)
        #pragma unroll
        for (int j = 0; j < 8; j++)
            #pragma unroll
            for (int c = 0; c < 4; c++) acc[i][j][c] = 0.f;

    const int NIT = K >> 5;

    auto load_tiles = [&](int stage, int k0) {
        #pragma unroll
        for (int s = 0; s < 4; s++) {
            int idx = tid + s * 128;
            int r = idx >> 2, q = idx & 3;
            uint32_t dst = saBase + (uint32_t)(stage * A_STG + r * GLDA + q * 8) * 2u;
            cp16(dst, &A[(m0 + r) * K + k0 + q * 8]);
        }
        #pragma unroll
        for (int s = 0; s < 4; s++) {
            int idx = tid + s * 128;
            int r = idx >> 4, q = idx & 15;
            uint32_t dst = sbBase + (uint32_t)(stage * B_STG + r * GLDB + q * 8) * 2u;
            cp16(dst, &B[(k0 + r) * N + n0 + q * 8]);
        }
    };

    load_tiles(0, 0);  cp_commit();
    load_tiles(1, 32); cp_commit();

    for (int it = 0; it < NIT; it++) {
        if (it + 1 < NIT) cp_wait1();
        else              cp_wait0();
        __syncthreads();

        if (it + 2 < NIT) {
            load_tiles((it + 2) % NSTG, (it + 2) << 5);
            cp_commit();
        }

        const int stage = it % NSTG;
        const uint32_t aTile = saBase + (uint32_t)(stage * A_STG) * 2u;
        const uint32_t bTile = sbBase + (uint32_t)(stage * B_STG) * 2u;

        #pragma unroll
        for (int kk = 0; kk < 32; kk += 16) {
            uint32_t a[4][4];
            #pragma unroll
            for (int i = 0; i < 4; i++)
                ldsm_x4(a[i], aTile + (uint32_t)((wm * 64 + i * 16) * GLDA + kk + aLane) * 2u);
            uint32_t b4[4][4];
            #pragma unroll
            for (int jn = 0; jn < 4; jn++)
                ldsm_x4_t(b4[jn], bTile + (uint32_t)(kk * GLDB + wn * 64 + jn * 16 + bLane) * 2u);
            #pragma unroll
            for (int i = 0; i < 4; i++) {
                #pragma unroll
                for (int jn = 0; jn < 4; jn++) {
                    mma_f16(acc[i][2 * jn],     a[i], b4[jn]);
                    mma_f16(acc[i][2 * jn + 1], a[i], b4[jn] + 2);
                }
            }
        }
    }

    if (halfOut) {
        __half* C = (__half*)Cv;
        #pragma unroll
        for (int i = 0; i < 4; i++) {
            int r0 = m0 + wm * 64 + i * 16 + gid;
            #pragma unroll
            for (int j = 0; j < 8; j++) {
                int col = n0 + wn * 64 + j * 8 + 2 * tig;
                float bx = bias[col], by = bias[col + 1];
                __half2 v0 = __floats2half2_rn(acc[i][j][0] + bx, acc[i][j][1] + by);
                __half2 v1 = __floats2half2_rn(acc[i][j][2] + bx, acc[i][j][3] + by);
                *reinterpret_cast<__half2*>(&C[r0 * N + col])       = v0;
                *reinterpret_cast<__half2*>(&C[(r0 + 8) * N + col]) = v1;
            }
        }
    } else {
        float* C = (float*)Cv;
        #pragma unroll
        for (int i = 0; i < 4; i++) {
            int r0 = m0 + wm * 64 + i * 16 + gid;
            #pragma unroll
            for (int j = 0; j < 8; j++) {
                int col = n0 + wn * 64 + j * 8 + 2 * tig;
                float bx = bias[col], by = bias[col + 1];
                float2 v0 = make_float2(acc[i][j][0] + bx, acc[i][j][1] + by);
                float2 v1 = make_float2(acc[i][j][2] + bx, acc[i][j][3] + by);
                *reinterpret_cast<float2*>(&C[r0 * N + col])       = v0;
                *reinterpret_cast<float2*>(&C[(r0 + 8) * N + col]) = v1;
            }
        }
    }
}

// ---------------------------------------------------------------------------
// Fused RoPE (q,k) + V copy, fp16 in (g_qkv16) -> head-major fp16 out.
// ---------------------------------------------------------------------------
__global__ __launch_bounds__(256) void rope_v(const __half* __restrict__ qkv,
                                              const int* __restrict__ pos)
{
    const int total = SEQ * 3 * NH * RD;
    int idx = blockIdx.x * blockDim.x + threadIdx.x;
    if (idx >= total) return;

    int d = idx % RD;
    int h = (idx / RD) % NH;
    int s = (idx / (RD * NH)) % 3;     // 0=q, 1=k, 2=v
    int t = idx / (RD * NH * 3);

    if (s == 2) {
        const uint32_t* src = reinterpret_cast<const uint32_t*>(
            &qkv[t * QKV_N + 2 * HIDDEN + h * HD + 2 * d]);
        *reinterpret_cast<uint32_t*>(&g_v16[(h * SEQ + t) * HD + 2 * d]) = *src;
        return;
    }

    int i = (d < 20) ? d : (d - 20);
    float p = (float)pos[t * 2 + ((d < 20) ? 0 : 1)];
    float ang = p * exp2f(-0.66438561897747246f * (float)i);
    float sv, cv;
    sincosf(ang, &sv, &cv);

    const __half* src = &qkv[t * QKV_N + s * HIDDEN + h * HD];
    float x0 = __half2float(src[d]);
    float x1 = __half2float(src[d + RD]);
    float y0 = x0 * cv - x1 * sv;
    float y1 = x1 * cv + x0 * sv;

    float sc = s ? 1.0f : 0.16130125483316624f;  // 80^-0.5 * log2(e)
    __half* dst = s ? g_k16 : g_q16;
    dst[(h * SEQ + t) * HD + d]      = __float2half(y0 * sc);
    dst[(h * SEQ + t) * HD + d + RD] = __float2half(y1 * sc);
}

// ---------------------------------------------------------------------------
// Flash attention, split-KV (KSPLIT=3), log2-domain softmax, one barrier/tile.
// Grid (SEQ/64, NH, KSPLIT), 128 threads.
// ---------------------------------------------------------------------------
#define LDH 88
#define KV_STG (64 * LDH)

__global__ __launch_bounds__(128, 4) void attn_kernel()
{
    __shared__ __half sK[2 * KV_STG];
    __shared__ __half sV[2 * KV_STG];

    const int h   = blockIdx.y;
    const int q0  = blockIdx.x * 64;
    const int z   = blockIdx.z;
    const int tid = threadIdx.x;
    const int w    = tid >> 5;
    const int lane = tid & 31;
    const int gid  = lane >> 2;
    const int tig  = lane & 3;
    const int j8   = lane & 7;
    const int grp  = lane >> 3;

    const uint32_t skBase = (uint32_t)__cvta_generic_to_shared(sK);
    const uint32_t svBase = (uint32_t)__cvta_generic_to_shared(sV);
    const int kOff = ((grp >> 1) * 8 + j8) * LDH + (grp & 1) * 8;
    const int vOff = ((grp & 1) * 8 + j8) * LDH + (grp >> 1) * 8;

    {
        const __half* qg = &g_q16[(h * SEQ + q0) * HD];
        #pragma unroll
        for (int i = tid; i < 640; i += 128) {
            int r = i / 10, c = i % 10;
            *reinterpret_cast<uint4*>(&sK[r * LDH + c * 8]) =
                *reinterpret_cast<const uint4*>(&qg[r * HD + c * 8]);
        }
    }
    __syncthreads();

    uint32_t qa[5][4];
    const int qrow = 16 * w + gid;
    #pragma unroll
    for (int t = 0; t < 5; t++) {
        qa[t][0] = *reinterpret_cast<uint32_t*>(&sK[ qrow      * LDH + t * 16 + 2 * tig]);
        qa[t][1] = *reinterpret_cast<uint32_t*>(&sK[(qrow + 8) * LDH + t * 16 + 2 * tig]);
        qa[t][2] = *reinterpret_cast<uint32_t*>(&sK[ qrow      * LDH + t * 16 + 2 * tig + 8]);
        qa[t][3] = *reinterpret_cast<uint32_t*>(&sK[(qrow + 8) * LDH + t * 16 + 2 * tig + 8]);
    }
    __syncthreads();   // Q extraction done; stage 0 free

    auto load_kv = [&](int stage, int k0) {
        const __half* kg = &g_k16[(h * SEQ + k0) * HD];
        const __half* vg = &g_v16[(h * SEQ + k0) * HD];
        #pragma unroll
        for (int s = 0; s < 5; s++) {
            int idx = tid + s * 128;
            int r = idx / 10, c = idx % 10;
            uint32_t off = (uint32_t)(stage * KV_STG + r * LDH + c * 8) * 2u;
            cp16(skBase + off, &kg[r * HD + c * 8]);
            cp16(svBase + off, &vg[r * HD + c * 8]);
        }
    };

    const int NT   = SEQ / 64 / KSPLIT;    // 16
    const int kbeg = z * (SEQ / KSPLIT);

    load_kv(0, kbeg);
    cp_commit();

    float m0r = -1e30f, m1r = -1e30f, l0 = 0.f, l1 = 0.f;
    float acc[10][4];
    #pragma unroll
    for (int n = 0; n < 10; n++)
        #pragma unroll
        for (int jj = 0; jj < 4; jj++) acc[n][jj] = 0.f;

    for (int kt = 0; kt < NT; kt++) {
        cp_wait0();
        __syncthreads();

        if (kt + 1 < NT) {
            load_kv((kt + 1) & 1, kbeg + (kt + 1) * 64);
            cp_commit();
        }

        const uint32_t kTile = skBase + (uint32_t)((kt & 1) * KV_STG) * 2u;
        const uint32_t vTile = svBase + (uint32_t)((kt & 1) * KV_STG) * 2u;

        // ---- S' = Q·log2e @ K^T ----
        float sf[8][4];
        #pragma unroll
        for (int n = 0; n < 8; n++)
            #pragma unroll
            for (int jj = 0; jj < 4; jj++) sf[n][jj] = 0.f;

        #pragma unroll
        for (int t = 0; t < 5; t++) {
            #pragma unroll
            for (int np = 0; np < 4; np++) {
                uint32_t b[4];
                ldsm_x4(b, kTile + (uint32_t)(np * 16 * LDH + t * 16 + kOff) * 2u);
                mma_f16(sf[2 * np],     qa[t], b);
                mma_f16(sf[2 * np + 1], qa[t], b + 2);
            }
        }

        // ---- Online softmax (log2 domain, h2exp2) ----
        float mx0 = -1e30f, mx1 = -1e30f;
        #pragma unroll
        for (int n = 0; n < 8; n++) {
            mx0 = fmaxf(mx0, fmaxf(sf[n][0], sf[n][1]));
            mx1 = fmaxf(mx1, fmaxf(sf[n][2], sf[n][3]));
        }
        #pragma unroll
        for (int o = 1; o <= 2; o <<= 1) {
            mx0 = fmaxf(mx0, __shfl_xor_sync(0xffffffffu, mx0, o));
            mx1 = fmaxf(mx1, __shfl_xor_sync(0xffffffffu, mx1, o));
        }
        float nm0 = fmaxf(m0r, mx0), nm1 = fmaxf(m1r, mx1);
        float c0 = exp2f(m0r - nm0), c1 = exp2f(m1r - nm1);
        m0r = nm0; m1r = nm1;

        uint32_t ph[8][2];
        float s0 = 0.f, s1 = 0.f;
        #pragma unroll
        for (int n = 0; n < 8; n++) {
            __half2 e0 = h2exp2(__floats2half2_rn(sf[n][0] - nm0, sf[n][1] - nm0));
            __half2 e1 = h2exp2(__floats2half2_rn(sf[n][2] - nm1, sf[n][3] - nm1));
            ph[n][0] = h2_as_u32(e0);
            ph[n][1] = h2_as_u32(e1);
            float2 f0 = __half22float2(e0);
            float2 f1 = __half22float2(e1);
            s0 += f0.x + f0.y;
            s1 += f1.x + f1.y;
        }
        #pragma unroll
        for (int o = 1; o <= 2; o <<= 1) {
            s0 += __shfl_xor_sync(0xffffffffu, s0, o);
            s1 += __shfl_xor_sync(0xffffffffu, s1, o);
        }
        l0 = l0 * c0 + s0;
        l1 = l1 * c1 + s1;
        #pragma unroll
        for (int n = 0; n < 10; n++) {
            acc[n][0] *= c0; acc[n][1] *= c0;
            acc[n][2] *= c1; acc[n][3] *= c1;
        }

        // ---- O += P @ V ----
        #pragma unroll
        for (int s = 0; s < 4; s++) {
            uint32_t pa[4];
            pa[0] = ph[2 * s][0];
            pa[1] = ph[2 * s][1];
            pa[2] = ph[2 * s + 1][0];
            pa[3] = ph[2 * s + 1][1];
            #pragma unroll
            for (int np = 0; np < 5; np++) {
                uint32_t b[4];
                ldsm_x4_t(b, vTile + (uint32_t)(s * 16 * LDH + np * 16 + vOff) * 2u);
                mma_f16(acc[2 * np],     pa, b);
                mma_f16(acc[2 * np + 1], pa, b + 2);
            }
        }
    }

    float* dst = &g_part[((z * NH + h) * SEQ + q0) * HD];
    #pragma unroll
    for (int n = 0; n < 10; n++) {
        int col = n * 8 + 2 * tig;
        *reinterpret_cast<float2*>(&dst[ qrow      * HD + col]) =
            make_float2(acc[n][0], acc[n][1]);
        *reinterpret_cast<float2*>(&dst[(qrow + 8) * HD + col]) =
            make_float2(acc[n][2], acc[n][3]);
    }
    if (tig == 0) {
        g_ml[(z * NH + h) * SEQ + q0 + qrow]     = make_float2(m0r, l0);
        g_ml[(z * NH + h) * SEQ + q0 + qrow + 8] = make_float2(m1r, l1);
    }
}

// ---------------------------------------------------------------------------
// Merge KSPLIT partials (m is log2-domain) -> fp16 attention output.
// ---------------------------------------------------------------------------
__global__ __launch_bounds__(256) void attn_merge()
{
    const int total = NH * SEQ * (HD / 2);
    int idx = blockIdx.x * blockDim.x + threadIdx.x;
    if (idx >= total) return;
    int d2 = idx % (HD / 2);
    int q  = (idx / (HD / 2)) % SEQ;
    int h  = idx / ((HD / 2) * SEQ);

    float2 ml[KSPLIT];
    float M = -1e30f;
    #pragma unroll
    for (int z = 0; z < KSPLIT; z++) {
        ml[z] = g_ml[(z * NH + h) * SEQ + q];
        M = fmaxf(M, ml[z].x);
    }
    float wsum = 0.f;
    float wz[KSPLIT];
    #pragma unroll
    for (int z = 0; z < KSPLIT; z++) {
        wz[z] = exp2f(ml[z].x - M);
        wsum += ml[z].y * wz[z];
    }
    float inv = 1.0f / wsum;

    float ox = 0.f, oy = 0.f;
    #pragma unroll
    for (int z = 0; z < KSPLIT; z++) {
        float2 p = *reinterpret_cast<const float2*>(
            &g_part[((z * NH + h) * SEQ + q) * HD + 2 * d2]);
        ox += p.x * wz[z];
        oy += p.y * wz[z];
    }
    *reinterpret_cast<__half2*>(&g_att16[q * HIDDEN + h * HD + 2 * d2]) =
        __floats2half2_rn(ox * inv, oy * inv);
}

// ---------------------------------------------------------------------------
extern "C" void kernel_launch(void* const* d_in, const int* in_sizes, int n_in,
                              void* d_out, int out_size)
{
    const float* hs    = (const float*)d_in[0];
    const int*   pos   = (const int*)d_in[1];
    const float* qkv_w = (const float*)d_in[2];
    const float* qkv_b = (const float*)d_in[3];
    const float* o_w   = (const float*)d_in[4];
    const float* o_b   = (const float*)d_in[5];
    float* out = (float*)d_out;

    __half* qkv16 = nullptr;
    __half* hs16  = nullptr;
    __half* qw16  = nullptr;
    __half* ow16  = nullptr;
    __half* att16 = nullptr;
    cudaGetSymbolAddress((void**)&qkv16, g_qkv16);
    cudaGetSymbolAddress((void**)&hs16,  g_hs16);
    cudaGetSymbolAddress((void**)&qw16,  g_qw16);
    cudaGetSymbolAddress((void**)&ow16,  g_ow16);
    cudaGetSymbolAddress((void**)&att16, g_att16);

    cudaFuncSetAttribute(hgemm_bias, cudaFuncAttributeMaxDynamicSharedMemorySize,
                         HG_SMEM);
    cudaFuncSetAttribute(hgemm_bias, cudaFuncAttributePreferredSharedMemoryCarveout,
                         cudaSharedmemCarveoutMaxShared);

    // 0) fused fp32 -> fp16 conversions (one launch)
    {
        cvt_all<<<(N8_ALL + 255) / 256, 256>>>(hs, qkv_w, o_w);
    }
    // 1) QKV GEMM + bias (fp16 out)
    {
        dim3 grid(QKV_N / 128, SEQ / 128);  // (30, 24)
        hgemm_bias<<<grid, 128, HG_SMEM>>>(hs16, qw16, qkv_b, qkv16,
                                           SEQ, QKV_N, HIDDEN, 1);
    }
    // 2) Fused RoPE (q,k) + V copy
    {
        int total = SEQ * 3 * NH * RD;
        rope_v<<<(total + 255) / 256, 256>>>(qkv16, pos);
    }
    // 3) Attention, split-KV=3 + merge (log2-domain softmax)
    {
        dim3 grid(SEQ / 64, NH, KSPLIT);  // (48, 16, 3)
        attn_kernel<<<grid, 128>>>();
        int totm = NH * SEQ * (HD / 2);
        attn_merge<<<(totm + 255) / 256, 256>>>();
    }
    // 4) O GEMM + bias (fp32 out)
    {
        dim3 grid(HIDDEN / 128, SEQ / 128);  // (10, 24)
        hgemm_bias<<<grid, 128, HG_SMEM>>>(att16, ow16, o_b, out,
                                           SEQ, HIDDEN, HIDDEN, 0);
    }
}

// round 15
// speedup vs baseline: 1.0839x; 1.0839x over previous
#include <cuda_runtime.h>
#include <cuda_fp16.h>
#include <math.h>
#include <stdint.h>

#define SEQ 3072
#define HIDDEN 1280
#define NH 16
#define HD 80
#define RD 40
#define QKV_N (3 * HIDDEN)
#define KSPLIT 2

// Scratch (allocation-free rule: __device__ globals)
__device__ __half g_qkv16[SEQ * QKV_N];     // QKV GEMM output (fp16)
__device__ __half g_hs16[SEQ * HIDDEN];     // hidden_states fp16
__device__ __half g_qw16[HIDDEN * QKV_N];   // qkv_w fp16
__device__ __half g_ow16[HIDDEN * HIDDEN];  // o_w fp16
__device__ __half g_att16[SEQ * HIDDEN];    // attention output fp16
__device__ __half g_q16[NH * SEQ * HD];     // head-major, rope'd, pre-scaled (log2 dom)
__device__ __half g_k16[NH * SEQ * HD];     // head-major, rope'd
__device__ __half g_v16[NH * SEQ * HD];     // head-major
__device__ float  g_part[KSPLIT * NH * SEQ * HD];  // unnormalized partial O
__device__ float2 g_ml[KSPLIT * NH * SEQ];         // per-row (max(log2), sum)

// ---------------------------------------------------------------------------
// helpers
// ---------------------------------------------------------------------------
__device__ __forceinline__ uint32_t h2_as_u32(__half2 h) {
    union { __half2 h2; uint32_t u; } cvt;
    cvt.h2 = h;
    return cvt.u;
}

__device__ __forceinline__ void mma_f16(float* d, const uint32_t* a, const uint32_t* b) {
    asm volatile(
        "mma.sync.aligned.m16n8k16.row.col.f32.f16.f16.f32 "
        "{%0,%1,%2,%3},{%4,%5,%6,%7},{%8,%9},{%0,%1,%2,%3};"
        : "+f"(d[0]), "+f"(d[1]), "+f"(d[2]), "+f"(d[3])
        : "r"(a[0]), "r"(a[1]), "r"(a[2]), "r"(a[3]),
          "r"(b[0]), "r"(b[1]));
}

__device__ __forceinline__ void ldsm_x4(uint32_t* r, uint32_t addr) {
    asm volatile("ldmatrix.sync.aligned.m8n8.x4.shared.b16 {%0,%1,%2,%3},[%4];"
        : "=r"(r[0]), "=r"(r[1]), "=r"(r[2]), "=r"(r[3]) : "r"(addr));
}

__device__ __forceinline__ void ldsm_x4_t(uint32_t* r, uint32_t addr) {
    asm volatile("ldmatrix.sync.aligned.m8n8.x4.trans.shared.b16 {%0,%1,%2,%3},[%4];"
        : "=r"(r[0]), "=r"(r[1]), "=r"(r[2]), "=r"(r[3]) : "r"(addr));
}

__device__ __forceinline__ void cp16(uint32_t dst, const void* src) {
    asm volatile("cp.async.ca.shared.global [%0], [%1], 16;" :: "r"(dst), "l"(src));
}
__device__ __forceinline__ void cp_commit() { asm volatile("cp.async.commit_group;"); }
__device__ __forceinline__ void cp_wait0() { asm volatile("cp.async.wait_group 0;"); }
__device__ __forceinline__ void cp_wait1() { asm volatile("cp.async.wait_group 1;"); }

// ---------------------------------------------------------------------------
// Fused fp32 -> fp16 convert for hs, qkv_w, o_w (one launch).
// ---------------------------------------------------------------------------
#define N8_HS  (SEQ * HIDDEN / 8)
#define N8_QW  (HIDDEN * QKV_N / 8)
#define N8_OW  (HIDDEN * HIDDEN / 8)
#define N8_ALL (N8_HS + N8_QW + N8_OW)

__global__ __launch_bounds__(256) void cvt_all(
    const float* __restrict__ hs, const float* __restrict__ qw,
    const float* __restrict__ ow)
{
    int idx = blockIdx.x * blockDim.x + threadIdx.x;
    if (idx >= N8_ALL) return;

    const float* src;
    __half* dst;
    int off;
    if (idx < N8_HS) {
        src = hs; dst = g_hs16; off = idx;
    } else if (idx < N8_HS + N8_QW) {
        src = qw; dst = g_qw16; off = idx - N8_HS;
    } else {
        src = ow; dst = g_ow16; off = idx - N8_HS - N8_QW;
    }

    float4 v0 = *reinterpret_cast<const float4*>(&src[off * 8]);
    float4 v1 = *reinterpret_cast<const float4*>(&src[off * 8 + 4]);
    __half2 h[4];
    h[0] = __floats2half2_rn(v0.x, v0.y);
    h[1] = __floats2half2_rn(v0.z, v0.w);
    h[2] = __floats2half2_rn(v1.x, v1.y);
    h[3] = __floats2half2_rn(v1.z, v1.w);
    *reinterpret_cast<uint4*>(&dst[off * 8]) = *reinterpret_cast<uint4*>(h);
}

// ---------------------------------------------------------------------------
// HGEMM: C[M,N] = A[M,K](fp16) @ B[K,N](fp16) + bias[N](fp32)
// BM=128 BN=128 BK=32, 128 threads = 4 warps (2m x 2n), warp tile m64 x n64.
// 3-stage cp.async ring, single barrier per iteration. (R13-proven: 91.6us)
// ---------------------------------------------------------------------------
#define GLDA 40
#define GLDB 136
#define A_STG (128 * GLDA)
#define B_STG (32 * GLDB)
#define NSTG 3
#define HG_SMEM ((NSTG * (A_STG + B_STG)) * 2)

__global__ __launch_bounds__(128) void hgemm_bias(
    const __half* __restrict__ A, const __half* __restrict__ B,
    const float* __restrict__ bias, void* __restrict__ Cv,
    int M, int N, int K, int halfOut)
{
    extern __shared__ __half hsm[];
    __half* sA = hsm;
    __half* sB = hsm + NSTG * A_STG;

    const int tid  = threadIdx.x;
    const int wid  = tid >> 5;
    const int lane = tid & 31;
    const int wm   = wid >> 1;
    const int wn   = wid & 1;
    const int gid  = lane >> 2;
    const int tig  = lane & 3;
    const int j8   = lane & 7;
    const int grp  = lane >> 3;

    const int m0 = blockIdx.y * 128;
    const int n0 = blockIdx.x * 128;

    const uint32_t saBase = (uint32_t)__cvta_generic_to_shared(sA);
    const uint32_t sbBase = (uint32_t)__cvta_generic_to_shared(sB);

    const int aLane = ((grp & 1) * 8 + j8) * GLDA + (grp >> 1) * 8;
    const int bLane = ((grp & 1) * 8 + j8) * GLDB + (grp >> 1) * 8;

    float acc[4][8][4];
    #pragma unroll
    for (int i = 0; i < 4; i++)
        #pragma unroll
        for (int j = 0; j < 8; j++)
            #pragma unroll
            for (int c = 0; c < 4; c++) acc[i][j][c] = 0.f;

    const int NIT = K >> 5;

    auto load_tiles = [&](int stage, int k0) {
        #pragma unroll
        for (int s = 0; s < 4; s++) {
            int idx = tid + s * 128;
            int r = idx >> 2, q = idx & 3;
            uint32_t dst = saBase + (uint32_t)(stage * A_STG + r * GLDA + q * 8) * 2u;
            cp16(dst, &A[(m0 + r) * K + k0 + q * 8]);
        }
        #pragma unroll
        for (int s = 0; s < 4; s++) {
            int idx = tid + s * 128;
            int r = idx >> 4, q = idx & 15;
            uint32_t dst = sbBase + (uint32_t)(stage * B_STG + r * GLDB + q * 8) * 2u;
            cp16(dst, &B[(k0 + r) * N + n0 + q * 8]);
        }
    };

    load_tiles(0, 0);  cp_commit();
    load_tiles(1, 32); cp_commit();

    for (int it = 0; it < NIT; it++) {
        if (it + 1 < NIT) cp_wait1();
        else              cp_wait0();
        __syncthreads();

        if (it + 2 < NIT) {
            load_tiles((it + 2) % NSTG, (it + 2) << 5);
            cp_commit();
        }

        const int stage = it % NSTG;
        const uint32_t aTile = saBase + (uint32_t)(stage * A_STG) * 2u;
        const uint32_t bTile = sbBase + (uint32_t)(stage * B_STG) * 2u;

        #pragma unroll
        for (int kk = 0; kk < 32; kk += 16) {
            uint32_t a[4][4];
            #pragma unroll
            for (int i = 0; i < 4; i++)
                ldsm_x4(a[i], aTile + (uint32_t)((wm * 64 + i * 16) * GLDA + kk + aLane) * 2u);
            uint32_t b4[4][4];
            #pragma unroll
            for (int jn = 0; jn < 4; jn++)
                ldsm_x4_t(b4[jn], bTile + (uint32_t)(kk * GLDB + wn * 64 + jn * 16 + bLane) * 2u);
            #pragma unroll
            for (int i = 0; i < 4; i++) {
                #pragma unroll
                for (int jn = 0; jn < 4; jn++) {
                    mma_f16(acc[i][2 * jn],     a[i], b4[jn]);
                    mma_f16(acc[i][2 * jn + 1], a[i], b4[jn] + 2);
                }
            }
        }
    }

    if (halfOut) {
        __half* C = (__half*)Cv;
        #pragma unroll
        for (int i = 0; i < 4; i++) {
            int r0 = m0 + wm * 64 + i * 16 + gid;
            #pragma unroll
            for (int j = 0; j < 8; j++) {
                int col = n0 + wn * 64 + j * 8 + 2 * tig;
                float bx = bias[col], by = bias[col + 1];
                __half2 v0 = __floats2half2_rn(acc[i][j][0] + bx, acc[i][j][1] + by);
                __half2 v1 = __floats2half2_rn(acc[i][j][2] + bx, acc[i][j][3] + by);
                *reinterpret_cast<__half2*>(&C[r0 * N + col])       = v0;
                *reinterpret_cast<__half2*>(&C[(r0 + 8) * N + col]) = v1;
            }
        }
    } else {
        float* C = (float*)Cv;
        #pragma unroll
        for (int i = 0; i < 4; i++) {
            int r0 = m0 + wm * 64 + i * 16 + gid;
            #pragma unroll
            for (int j = 0; j < 8; j++) {
                int col = n0 + wn * 64 + j * 8 + 2 * tig;
                float bx = bias[col], by = bias[col + 1];
                float2 v0 = make_float2(acc[i][j][0] + bx, acc[i][j][1] + by);
                float2 v1 = make_float2(acc[i][j][2] + bx, acc[i][j][3] + by);
                *reinterpret_cast<float2*>(&C[r0 * N + col])       = v0;
                *reinterpret_cast<float2*>(&C[(r0 + 8) * N + col]) = v1;
            }
        }
    }
}

// ---------------------------------------------------------------------------
// Fused RoPE (q,k) + V copy, fp16 in (g_qkv16) -> head-major fp16 out.
// __sincosf fast intrinsic (|ang| < 64, abs err ~1e-5 — negligible vs 1e-3).
// ---------------------------------------------------------------------------
__global__ __launch_bounds__(256) void rope_v(const __half* __restrict__ qkv,
                                              const int* __restrict__ pos)
{
    const int total = SEQ * 3 * NH * RD;
    int idx = blockIdx.x * blockDim.x + threadIdx.x;
    if (idx >= total) return;

    int d = idx % RD;
    int h = (idx / RD) % NH;
    int s = (idx / (RD * NH)) % 3;     // 0=q, 1=k, 2=v
    int t = idx / (RD * NH * 3);

    if (s == 2) {
        const uint32_t* src = reinterpret_cast<const uint32_t*>(
            &qkv[t * QKV_N + 2 * HIDDEN + h * HD + 2 * d]);
        *reinterpret_cast<uint32_t*>(&g_v16[(h * SEQ + t) * HD + 2 * d]) = *src;
        return;
    }

    int i = (d < 20) ? d : (d - 20);
    float p = (float)pos[t * 2 + ((d < 20) ? 0 : 1)];
    float ang = p * exp2f(-0.66438561897747246f * (float)i);
    float sv, cv;
    __sincosf(ang, &sv, &cv);

    const __half* src = &qkv[t * QKV_N + s * HIDDEN + h * HD];
    float x0 = __half2float(src[d]);
    float x1 = __half2float(src[d + RD]);
    float y0 = x0 * cv - x1 * sv;
    float y1 = x1 * cv + x0 * sv;

    float sc = s ? 1.0f : 0.16130125483316624f;  // 80^-0.5 * log2(e)
    __half* dst = s ? g_k16 : g_q16;
    dst[(h * SEQ + t) * HD + d]      = __float2half(y0 * sc);
    dst[(h * SEQ + t) * HD + d + RD] = __float2half(y1 * sc);
}

// ---------------------------------------------------------------------------
// Flash attention, split-KV=2, log2-domain softmax, one barrier per tile.
// Grid (SEQ/64, NH, KSPLIT), 128 threads.
// ---------------------------------------------------------------------------
#define LDH 88
#define KV_STG (64 * LDH)

__global__ __launch_bounds__(128, 4) void attn_kernel()
{
    __shared__ __half sK[2 * KV_STG];
    __shared__ __half sV[2 * KV_STG];

    const int h   = blockIdx.y;
    const int q0  = blockIdx.x * 64;
    const int z   = blockIdx.z;
    const int tid = threadIdx.x;
    const int w    = tid >> 5;
    const int lane = tid & 31;
    const int gid  = lane >> 2;
    const int tig  = lane & 3;
    const int j8   = lane & 7;
    const int grp  = lane >> 3;

    const uint32_t skBase = (uint32_t)__cvta_generic_to_shared(sK);
    const uint32_t svBase = (uint32_t)__cvta_generic_to_shared(sV);
    const int kOff = ((grp >> 1) * 8 + j8) * LDH + (grp & 1) * 8;
    const int vOff = ((grp & 1) * 8 + j8) * LDH + (grp >> 1) * 8;

    {
        const __half* qg = &g_q16[(h * SEQ + q0) * HD];
        #pragma unroll
        for (int i = tid; i < 640; i += 128) {
            int r = i / 10, c = i % 10;
            *reinterpret_cast<uint4*>(&sK[r * LDH + c * 8]) =
                *reinterpret_cast<const uint4*>(&qg[r * HD + c * 8]);
        }
    }
    __syncthreads();

    uint32_t qa[5][4];
    const int qrow = 16 * w + gid;
    #pragma unroll
    for (int t = 0; t < 5; t++) {
        qa[t][0] = *reinterpret_cast<uint32_t*>(&sK[ qrow      * LDH + t * 16 + 2 * tig]);
        qa[t][1] = *reinterpret_cast<uint32_t*>(&sK[(qrow + 8) * LDH + t * 16 + 2 * tig]);
        qa[t][2] = *reinterpret_cast<uint32_t*>(&sK[ qrow      * LDH + t * 16 + 2 * tig + 8]);
        qa[t][3] = *reinterpret_cast<uint32_t*>(&sK[(qrow + 8) * LDH + t * 16 + 2 * tig + 8]);
    }
    __syncthreads();   // Q extraction done; stage 0 free

    auto load_kv = [&](int stage, int k0) {
        const __half* kg = &g_k16[(h * SEQ + k0) * HD];
        const __half* vg = &g_v16[(h * SEQ + k0) * HD];
        #pragma unroll
        for (int s = 0; s < 5; s++) {
            int idx = tid + s * 128;
            int r = idx / 10, c = idx % 10;
            uint32_t off = (uint32_t)(stage * KV_STG + r * LDH + c * 8) * 2u;
            cp16(skBase + off, &kg[r * HD + c * 8]);
            cp16(svBase + off, &vg[r * HD + c * 8]);
        }
    };

    const int NT   = SEQ / 64 / KSPLIT;    // 24
    const int kbeg = z * (SEQ / KSPLIT);

    load_kv(0, kbeg);
    cp_commit();

    float m0r = -1e30f, m1r = -1e30f, l0 = 0.f, l1 = 0.f;
    float acc[10][4];
    #pragma unroll
    for (int n = 0; n < 10; n++)
        #pragma unroll
        for (int jj = 0; jj < 4; jj++) acc[n][jj] = 0.f;

    for (int kt = 0; kt < NT; kt++) {
        cp_wait0();
        __syncthreads();

        if (kt + 1 < NT) {
            load_kv((kt + 1) & 1, kbeg + (kt + 1) * 64);
            cp_commit();
        }

        const uint32_t kTile = skBase + (uint32_t)((kt & 1) * KV_STG) * 2u;
        const uint32_t vTile = svBase + (uint32_t)((kt & 1) * KV_STG) * 2u;

        // ---- S' = Q·log2e @ K^T ----
        float sf[8][4];
        #pragma unroll
        for (int n = 0; n < 8; n++)
            #pragma unroll
            for (int jj = 0; jj < 4; jj++) sf[n][jj] = 0.f;

        #pragma unroll
        for (int t = 0; t < 5; t++) {
            #pragma unroll
            for (int np = 0; np < 4; np++) {
                uint32_t b[4];
                ldsm_x4(b, kTile + (uint32_t)(np * 16 * LDH + t * 16 + kOff) * 2u);
                mma_f16(sf[2 * np],     qa[t], b);
                mma_f16(sf[2 * np + 1], qa[t], b + 2);
            }
        }

        // ---- Online softmax (log2 domain, h2exp2) ----
        float mx0 = -1e30f, mx1 = -1e30f;
        #pragma unroll
        for (int n = 0; n < 8; n++) {
            mx0 = fmaxf(mx0, fmaxf(sf[n][0], sf[n][1]));
            mx1 = fmaxf(mx1, fmaxf(sf[n][2], sf[n][3]));
        }
        #pragma unroll
        for (int o = 1; o <= 2; o <<= 1) {
            mx0 = fmaxf(mx0, __shfl_xor_sync(0xffffffffu, mx0, o));
            mx1 = fmaxf(mx1, __shfl_xor_sync(0xffffffffu, mx1, o));
        }
        float nm0 = fmaxf(m0r, mx0), nm1 = fmaxf(m1r, mx1);
        float c0 = exp2f(m0r - nm0), c1 = exp2f(m1r - nm1);
        m0r = nm0; m1r = nm1;

        uint32_t ph[8][2];
        float s0 = 0.f, s1 = 0.f;
        #pragma unroll
        for (int n = 0; n < 8; n++) {
            __half2 e0 = h2exp2(__floats2half2_rn(sf[n][0] - nm0, sf[n][1] - nm0));
            __half2 e1 = h2exp2(__floats2half2_rn(sf[n][2] - nm1, sf[n][3] - nm1));
            ph[n][0] = h2_as_u32(e0);
            ph[n][1] = h2_as_u32(e1);
            float2 f0 = __half22float2(e0);
            float2 f1 = __half22float2(e1);
            s0 += f0.x + f0.y;
            s1 += f1.x + f1.y;
        }
        #pragma unroll
        for (int o = 1; o <= 2; o <<= 1) {
            s0 += __shfl_xor_sync(0xffffffffu, s0, o);
            s1 += __shfl_xor_sync(0xffffffffu, s1, o);
        }
        l0 = l0 * c0 + s0;
        l1 = l1 * c1 + s1;
        #pragma unroll
        for (int n = 0; n < 10; n++) {
            acc[n][0] *= c0; acc[n][1] *= c0;
            acc[n][2] *= c1; acc[n][3] *= c1;
        }

        // ---- O += P @ V ----
        #pragma unroll
        for (int s = 0; s < 4; s++) {
            uint32_t pa[4];
            pa[0] = ph[2 * s][0];
            pa[1] = ph[2 * s][1];
            pa[2] = ph[2 * s + 1][0];
            pa[3] = ph[2 * s + 1][1];
            #pragma unroll
            for (int np = 0; np < 5; np++) {
                uint32_t b[4];
                ldsm_x4_t(b, vTile + (uint32_t)(s * 16 * LDH + np * 16 + vOff) * 2u);
                mma_f16(acc[2 * np],     pa, b);
                mma_f16(acc[2 * np + 1], pa, b + 2);
            }
        }
    }

    float* dst = &g_part[((z * NH + h) * SEQ + q0) * HD];
    #pragma unroll
    for (int n = 0; n < 10; n++) {
        int col = n * 8 + 2 * tig;
        *reinterpret_cast<float2*>(&dst[ qrow      * HD + col]) =
            make_float2(acc[n][0], acc[n][1]);
        *reinterpret_cast<float2*>(&dst[(qrow + 8) * HD + col]) =
            make_float2(acc[n][2], acc[n][3]);
    }
    if (tig == 0) {
        g_ml[(z * NH + h) * SEQ + q0 + qrow]     = make_float2(m0r, l0);
        g_ml[(z * NH + h) * SEQ + q0 + qrow + 8] = make_float2(m1r, l1);
    }
}

// ---------------------------------------------------------------------------
// Merge split-KV partials (m is log2-domain) -> fp16 attention output.
// One thread per 4 output elems (float4 partial reads).
// ---------------------------------------------------------------------------
__global__ __launch_bounds__(256) void attn_merge()
{
    const int total = NH * SEQ * (HD / 4);
    int idx = blockIdx.x * blockDim.x + threadIdx.x;
    if (idx >= total) return;
    int d4 = idx % (HD / 4);
    int q  = (idx / (HD / 4)) % SEQ;
    int h  = idx / ((HD / 4) * SEQ);

    float2 ml0 = g_ml[(0 * NH + h) * SEQ + q];
    float2 ml1 = g_ml[(1 * NH + h) * SEQ + q];
    float M  = fmaxf(ml0.x, ml1.x);
    float w0 = exp2f(ml0.x - M);
    float w1 = exp2f(ml1.x - M);
    float inv = 1.0f / (ml0.y * w0 + ml1.y * w1);
    w0 *= inv;
    w1 *= inv;

    float4 p0 = *reinterpret_cast<const float4*>(
        &g_part[((0 * NH + h) * SEQ + q) * HD + 4 * d4]);
    float4 p1 = *reinterpret_cast<const float4*>(
        &g_part[((1 * NH + h) * SEQ + q) * HD + 4 * d4]);

    __half2 o0 = __floats2half2_rn(p0.x * w0 + p1.x * w1, p0.y * w0 + p1.y * w1);
    __half2 o1 = __floats2half2_rn(p0.z * w0 + p1.z * w1, p0.w * w0 + p1.w * w1);
    __half2* dst = reinterpret_cast<__half2*>(&g_att16[q * HIDDEN + h * HD + 4 * d4]);
    dst[0] = o0;
    dst[1] = o1;
}

// ---------------------------------------------------------------------------
extern "C" void kernel_launch(void* const* d_in, const int* in_sizes, int n_in,
                              void* d_out, int out_size)
{
    const float* hs    = (const float*)d_in[0];
    const int*   pos   = (const int*)d_in[1];
    const float* qkv_w = (const float*)d_in[2];
    const float* qkv_b = (const float*)d_in[3];
    const float* o_w   = (const float*)d_in[4];
    const float* o_b   = (const float*)d_in[5];
    float* out = (float*)d_out;

    __half* qkv16 = nullptr;
    __half* hs16  = nullptr;
    __half* qw16  = nullptr;
    __half* ow16  = nullptr;
    __half* att16 = nullptr;
    cudaGetSymbolAddress((void**)&qkv16, g_qkv16);
    cudaGetSymbolAddress((void**)&hs16,  g_hs16);
    cudaGetSymbolAddress((void**)&qw16,  g_qw16);
    cudaGetSymbolAddress((void**)&ow16,  g_ow16);
    cudaGetSymbolAddress((void**)&att16, g_att16);

    cudaFuncSetAttribute(hgemm_bias, cudaFuncAttributeMaxDynamicSharedMemorySize,
                         HG_SMEM);

    // 0) fused fp32 -> fp16 conversions (one launch)
    {
        cvt_all<<<(N8_ALL + 255) / 256, 256>>>(hs, qkv_w, o_w);
    }
    // 1) QKV GEMM + bias (fp16 out)
    {
        dim3 grid(QKV_N / 128, SEQ / 128);  // (30, 24)
        hgemm_bias<<<grid, 128, HG_SMEM>>>(hs16, qw16, qkv_b, qkv16,
                                           SEQ, QKV_N, HIDDEN, 1);
    }
    // 2) Fused RoPE (q,k) + V copy
    {
        int total = SEQ * 3 * NH * RD;
        rope_v<<<(total + 255) / 256, 256>>>(qkv16, pos);
    }
    // 3) Attention, split-KV=2 + merge (log2-domain softmax)
    {
        dim3 grid(SEQ / 64, NH, KSPLIT);  // (48, 16, 2)
        attn_kernel<<<grid, 128>>>();
        int totm = NH * SEQ * (HD / 4);
        attn_merge<<<(totm + 255) / 256, 256>>>();
    }
    // 4) O GEMM + bias (fp32 out)
    {
        dim3 grid(HIDDEN / 128, SEQ / 128);  // (10, 24)
        hgemm_bias<<<grid, 128, HG_SMEM>>>(att16, ow16, o_b, out,
                                           SEQ, HIDDEN, HIDDEN, 0);
    }
}